// round 9
// baseline (speedup 1.0000x reference)
#include <cuda_runtime.h>

#define NN    128
#define BATCH 2
#define LL    2048
#define CH    32          // chunk length S
#define NG    (LL/CH)     // 64 chunks per batch
#define NT    512         // threads for recurrence kernels
#define PIT   129         // smem pitch (conflict-free)

// ---- device scratch (no allocation allowed) ----
__device__ float g_Ad[NN*NN];
__device__ float g_Bd[NN];
__device__ float g_pow[2][NN*NN];      // for Ad^S via squaring
__device__ float g_h[BATCH*NG*NN];     // local chunk contributions
__device__ float g_bound[BATCH*NG*NN]; // state entering each chunk

// ============================================================
// Kernel 1: discretize via divide-and-conquer triangular inverse.
// P1 = I - 0.5A is LOWER TRIANGULAR.
// ============================================================
__global__ __launch_bounds__(1024, 1) void k_disc(const float* __restrict__ A,
                                                  const float* __restrict__ B) {
    extern __shared__ float sm[];
    float* sP = sm;                 // NN*PIT
    float* sM = sm + NN*PIT;        // NN*PIT
    float* sT = sm + 2*NN*PIT;      // 4096 temp
    int tid = threadIdx.x;

    for (int idx = tid; idx < NN*NN; idx += 1024) {
        int i = idx >> 7, j = idx & (NN-1);
        float iv = (i == j) ? 1.0f : 0.0f;
        sP[i*PIT + j] = iv - 0.5f * A[idx];
        sM[i*PIT + j] = 0.0f;
    }
    __syncthreads();

    if (tid < 128) {
        int blk = tid >> 3, col = tid & 7;
        int b0 = blk * 8;
        float x[8];
        #pragma unroll
        for (int i = 0; i < 8; i++) x[i] = 0.0f;
        for (int i = col; i < 8; i++) {
            float v = (i == col) ? 1.0f : 0.0f;
            for (int k = col; k < i; k++)
                v -= sP[(b0+i)*PIT + b0 + k] * x[k];
            x[i] = v / sP[(b0+i)*PIT + b0 + i];
        }
        #pragma unroll
        for (int i = 0; i < 8; i++)
            sM[(b0+i)*PIT + b0 + col] = x[i];
    }
    __syncthreads();

    for (int s = 8; s <= 64; s <<= 1) {
        int npairs = NN / (2*s);
        int total  = npairs * s * s;
        for (int idx = tid; idx < total; idx += 1024) {
            int p = idx / (s*s);
            int rem = idx - p*s*s;
            int i = rem / s, j = rem - i*s;
            int r0 = 2*p*s;
            float acc = 0.0f;
            for (int k = 0; k < s; k++)
                acc = fmaf(sM[(r0+s+i)*PIT + r0+s+k],
                           sP[(r0+s+k)*PIT + r0+j], acc);
            sT[idx] = acc;
        }
        __syncthreads();
        for (int idx = tid; idx < total; idx += 1024) {
            int p = idx / (s*s);
            int rem = idx - p*s*s;
            int i = rem / s, j = rem - i*s;
            int r0 = 2*p*s;
            float acc = 0.0f;
            const float* tp = sT + p*s*s + i*s;
            for (int k = 0; k < s; k++)
                acc = fmaf(tp[k], sM[(r0+k)*PIT + r0+j], acc);
            sM[(r0+s+i)*PIT + r0+j] = -acc;
        }
        __syncthreads();
    }

    for (int idx = tid; idx < NN*NN; idx += 1024) {
        int i = idx >> 7, j = idx & (NN-1);
        float m = sM[i*PIT + j];
        float ad = 2.0f * m - ((i == j) ? 1.0f : 0.0f);
        g_Ad[idx] = ad;
        g_pow[0][idx] = ad;
    }
    if (tid < NN) {
        float acc = 0.0f;
        for (int j = 0; j <= tid; j++)
            acc = fmaf(sM[tid*PIT + j], B[j], acc);
        g_Bd[tid] = acc;
    }
}

// ============================================================
// Kernel 2: matrix squaring v3. One output row per block, 256 thr.
// Stage full src row-major (float4 copy). Warp w = k-slice of 16,
// lane = col4. Per k: ONE LDS.128 (cols) + broadcast arow (hoisted
// float4). 8-way slice reduce at the end.
// ============================================================
__global__ __launch_bounds__(256, 1) void k_sq(int srcSel, int dstSel) {
    extern __shared__ float smq[];
    float*  sB  = smq;                         // NN*NN
    float4* red = (float4*)(smq + NN*NN);      // 8*32 float4
    const float4* s4 = (const float4*)g_pow[srcSel];
    float* __restrict__ dst = g_pow[dstSel];
    int i = blockIdx.x, tid = threadIdx.x;
    float4* sB4 = (float4*)sB;
    #pragma unroll
    for (int u = 0; u < 16; u++)
        sB4[tid + 256*u] = __ldg(s4 + tid + 256*u);
    __syncthreads();
    int s  = tid >> 5;        // k-slice (warp-uniform)
    int c4 = tid & 31;        // float4 column
    const float4* arow4 = (const float4*)(sB + i*NN) + s*4;   // 16 a's
    float4 a0 = arow4[0], a1 = arow4[1], a2 = arow4[2], a3 = arow4[3];
    float av[16] = {a0.x,a0.y,a0.z,a0.w, a1.x,a1.y,a1.z,a1.w,
                    a2.x,a2.y,a2.z,a2.w, a3.x,a3.y,a3.z,a3.w};
    float4 acc = make_float4(0.f,0.f,0.f,0.f);
    #pragma unroll
    for (int u = 0; u < 16; u++) {
        float4 bv = sB4[(s*16 + u)*32 + c4];
        float  a  = av[u];
        acc.x = fmaf(a, bv.x, acc.x);
        acc.y = fmaf(a, bv.y, acc.y);
        acc.z = fmaf(a, bv.z, acc.z);
        acc.w = fmaf(a, bv.w, acc.w);
    }
    red[s*32 + c4] = acc;
    __syncthreads();
    if (tid < 32) {
        float4 t = red[tid];
        #pragma unroll
        for (int s2 = 1; s2 < 8; s2++) {
            float4 v = red[s2*32 + tid];
            t.x += v.x; t.y += v.y; t.z += v.z; t.w += v.w;
        }
        ((float4*)(dst + i*NN))[tid] = t;
    }
}

// ============================================================
// Recurrence step layout (phaseA/phaseB/fusedC pass1):
//   warp w owns rows 8w..8w+7; lane = (row_lo<<2)|kq, kq = k-quarter.
//   Thread: 32 FMAs over its quarter, 2x SHFL.XOR reduce, kq==0 lane
//   writes the row. Double-buffered state -> ONE barrier per step.
// ============================================================

// Kernel 3: phase A — local chunk contributions from zero state.
__global__ __launch_bounds__(NT, 1) void k_phaseA(const float* __restrict__ f) {
    extern __shared__ float sm[];
    float* sAd = sm;               // NN*PIT
    float* sc0 = sAd + NN*PIT;     // NN
    float* sc1 = sc0 + NN;         // NN
    float* sf  = sc1 + NN;         // CH
    int tid = threadIdx.x;
    int w = tid >> 5, lane = tid & 31;
    int row = 8*w + (lane >> 2);
    int kq  = lane & 3;
    int g = blockIdx.x, b = blockIdx.y;

    for (int idx = tid; idx < NN*NN; idx += NT) {
        int i = idx >> 7, j = idx & (NN-1);
        sAd[i*PIT + j] = g_Ad[idx];
    }
    if (tid < CH) sf[tid] = f[b*LL + g*CH + tid];
    if (tid < NN) sc0[tid] = 0.0f;
    __syncthreads();

    float a[32];
    #pragma unroll
    for (int u = 0; u < 32; u++) a[u] = sAd[row*PIT + 32*kq + u];
    float bd = (kq == 0) ? g_Bd[row] : 0.0f;

    float* bufs[2] = {sc0, sc1};
    int p = 0;
    float cn = 0.0f;
    for (int t = 0; t < CH; t++) {
        const float4* sc4 = (const float4*)bufs[p];
        float acc0 = (kq == 0) ? bd * sf[t] : 0.f;
        float acc1 = 0.f, acc2 = 0.f, acc3 = 0.f;
        #pragma unroll
        for (int u4 = 0; u4 < 8; u4++) {
            float4 v = sc4[8*kq + u4];
            acc0 = fmaf(a[4*u4+0], v.x, acc0);
            acc1 = fmaf(a[4*u4+1], v.y, acc1);
            acc2 = fmaf(a[4*u4+2], v.z, acc2);
            acc3 = fmaf(a[4*u4+3], v.w, acc3);
        }
        float val = (acc0 + acc1) + (acc2 + acc3);
        val += __shfl_xor_sync(0xffffffffu, val, 1);
        val += __shfl_xor_sync(0xffffffffu, val, 2);
        if (kq == 0) { cn = val; bufs[p^1][row] = val; }
        __syncthreads();
        p ^= 1;
    }
    if (kq == 0) g_h[(b*NG + g)*NN + row] = cn;
}

// Kernel 4: boundary prefix.  C_{g+1} = Ad^S * C_g + h_g.
__global__ __launch_bounds__(NT, 1) void k_phaseB() {
    extern __shared__ float sm[];
    float* sA  = sm;               // NN*PIT
    float* sc0 = sA + NN*PIT;      // NN
    float* sc1 = sc0 + NN;         // NN
    int tid = threadIdx.x;
    int w = tid >> 5, lane = tid & 31;
    int row = 8*w + (lane >> 2);
    int kq  = lane & 3;
    int b = blockIdx.x;
    const float* AdS = g_pow[1];   // Ad^32
    for (int idx = tid; idx < NN*NN; idx += NT) {
        int i = idx >> 7, j = idx & (NN-1);
        sA[i*PIT + j] = AdS[idx];
    }
    if (tid < NN) sc0[tid] = 0.0f;
    __syncthreads();
    float a[32];
    #pragma unroll
    for (int u = 0; u < 32; u++) a[u] = sA[row*PIT + 32*kq + u];

    float* bufs[2] = {sc0, sc1};
    int p = 0;
    float cn = 0.0f;
    for (int g = 0; g < NG; g++) {
        if (kq == 0) g_bound[(b*NG + g)*NN + row] = cn;
        const float4* sc4 = (const float4*)bufs[p];
        float acc0 = (kq == 0) ? __ldg(g_h + (b*NG + g)*NN + row) : 0.f;
        float acc1 = 0.f, acc2 = 0.f, acc3 = 0.f;
        #pragma unroll
        for (int u4 = 0; u4 < 8; u4++) {
            float4 v = sc4[8*kq + u4];
            acc0 = fmaf(a[4*u4+0], v.x, acc0);
            acc1 = fmaf(a[4*u4+1], v.y, acc1);
            acc2 = fmaf(a[4*u4+2], v.z, acc2);
            acc3 = fmaf(a[4*u4+3], v.w, acc3);
        }
        float val = (acc0 + acc1) + (acc2 + acc3);
        val += __shfl_xor_sync(0xffffffffu, val, 1);
        val += __shfl_xor_sync(0xffffffffu, val, 2);
        if (kq == 0) { cn = val; bufs[p^1][row] = val; }
        __syncthreads();
        p ^= 1;
    }
}

// Kernel 5: FUSED phase C + expand, two-pass.
__global__ __launch_bounds__(NT, 1) void k_fusedC(const float* __restrict__ f,
                                                  const float* __restrict__ Cv,
                                                  const float* __restrict__ Dv,
                                                  float* __restrict__ ys,
                                                  float* __restrict__ cfin) {
    extern __shared__ float sm[];
    float* sAd = sm;               // NN*PIT
    float* sSt = sAd + NN*PIT;     // CH*NN states
    float* sc0 = sSt + CH*NN;      // NN
    float* sc1 = sc0 + NN;         // NN
    float* sf  = sc1 + NN;         // CH
    float* sC  = sf + CH;          // NN
    int tid = threadIdx.x;
    int w = tid >> 5, lane = tid & 31;
    int row = 8*w + (lane >> 2);
    int kq  = lane & 3;
    int g = blockIdx.x, b = blockIdx.y;

    for (int idx = tid; idx < NN*NN; idx += NT) {
        int i = idx >> 7, j = idx & (NN-1);
        sAd[i*PIT + j] = g_Ad[idx];
    }
    if (tid < CH) sf[tid] = f[b*LL + g*CH + tid];
    if (tid < NN) {
        sC[tid]  = Cv[tid];
        sc0[tid] = g_bound[(b*NG + g)*NN + tid];
    }
    __syncthreads();

    float a[32];
    #pragma unroll
    for (int u = 0; u < 32; u++) a[u] = sAd[row*PIT + 32*kq + u];
    float bd  = (kq == 0) ? g_Bd[row] : 0.0f;
    float dv0 = Dv[0];

    // ---- pass 1: recurrence into sSt (one barrier/step) ----
    float* bufs[2] = {sc0, sc1};
    int p = 0;
    for (int t = 0; t < CH; t++) {
        const float4* sc4 = (const float4*)bufs[p];
        float acc0 = (kq == 0) ? bd * sf[t] : 0.f;
        float acc1 = 0.f, acc2 = 0.f, acc3 = 0.f;
        #pragma unroll
        for (int u4 = 0; u4 < 8; u4++) {
            float4 v = sc4[8*kq + u4];
            acc0 = fmaf(a[4*u4+0], v.x, acc0);
            acc1 = fmaf(a[4*u4+1], v.y, acc1);
            acc2 = fmaf(a[4*u4+2], v.z, acc2);
            acc3 = fmaf(a[4*u4+3], v.w, acc3);
        }
        float val = (acc0 + acc1) + (acc2 + acc3);
        val += __shfl_xor_sync(0xffffffffu, val, 1);
        val += __shfl_xor_sync(0xffffffffu, val, 2);
        if (kq == 0) { bufs[p^1][row] = val; sSt[t*NN + row] = val; }
        __syncthreads();
        p ^= 1;
    }

    // ---- pass 2: barrier-free streaming store ----
    float cn_[8];
    int nb = tid >> 5;
    #pragma unroll
    for (int it = 0; it < 8; it++) cn_[it] = sC[nb + 16*it];
    int lane2 = tid & 31;
    float4* outbase = (float4*)(ys + (size_t)(b*LL + g*CH) * NN * NN);
    const float4* st4 = (const float4*)sSt;

    for (int t = 0; t < CH; t++) {
        float4 cv = st4[t*(NN/4) + lane2];
        float  df = dv0 * sf[t];
        float4* out = outbase + (size_t)t * (NN*NN/4);
        #pragma unroll
        for (int it = 0; it < 8; it++) {
            int idx = tid + NT*it;
            float4 v;
            v.x = fmaf(cn_[it], cv.x, df);
            v.y = fmaf(cn_[it], cv.y, df);
            v.z = fmaf(cn_[it], cv.z, df);
            v.w = fmaf(cn_[it], cv.w, df);
            __stcs(&out[idx], v);
        }
    }
    if (cfin != nullptr && g == NG-1 && tid < NN)
        cfin[b*NN + tid] = sSt[(CH-1)*NN + tid];
}

// ============================================================
extern "C" void kernel_launch(void* const* d_in, const int* in_sizes, int n_in,
                              void* d_out, int out_size) {
    const float* f = (const float*)d_in[0];
    const float* A = (const float*)d_in[1];
    const float* B = (const float*)d_in[2];
    const float* C = (const float*)d_in[3];
    const float* D = (const float*)d_in[4];
    float* out = (float*)d_out;

    const long long ysz = (long long)BATCH * LL * NN * NN;   // 67108864
    const int cf = BATCH * NN;                               // 256
    float* cfin = nullptr;
    float* ys   = out;
    if ((long long)out_size == ysz + cf) { cfin = out; ys = out + cf; }

    const int smem_disc = (2*NN*PIT + 4096)*4;
    const int smem_sq   = (NN*NN + 8*32*4)*4;                    // 69632
    const int smem_pA   = (NN*PIT + 2*NN + CH)*4;
    const int smem_pB   = (NN*PIT + 2*NN)*4;
    const int smem_fC   = (NN*PIT + CH*NN + 2*NN + CH + NN)*4;
    cudaFuncSetAttribute(k_disc,   cudaFuncAttributeMaxDynamicSharedMemorySize, smem_disc);
    cudaFuncSetAttribute(k_sq,     cudaFuncAttributeMaxDynamicSharedMemorySize, smem_sq);
    cudaFuncSetAttribute(k_phaseA, cudaFuncAttributeMaxDynamicSharedMemorySize, smem_pA);
    cudaFuncSetAttribute(k_phaseB, cudaFuncAttributeMaxDynamicSharedMemorySize, smem_pB);
    cudaFuncSetAttribute(k_fusedC, cudaFuncAttributeMaxDynamicSharedMemorySize, smem_fC);

    // 1) discretize (D&C triangular inverse)
    k_disc<<<1, 1024, smem_disc>>>(A, B);
    // 2) phase A — local chunk contributions
    dim3 gA(NG, BATCH);
    k_phaseA<<<gA, NT, smem_pA>>>(f);
    // 3) Ad^32 via 5 squarings
    k_sq<<<NN, 256, smem_sq>>>(0, 1);
    k_sq<<<NN, 256, smem_sq>>>(1, 0);
    k_sq<<<NN, 256, smem_sq>>>(0, 1);
    k_sq<<<NN, 256, smem_sq>>>(1, 0);
    k_sq<<<NN, 256, smem_sq>>>(0, 1);
    // 4) boundary prefix
    k_phaseB<<<BATCH, NT, smem_pB>>>();
    // 5) fused phase C + expand
    k_fusedC<<<gA, NT, smem_fC>>>(f, C, D, ys, cfin);
}

// round 10
// speedup vs baseline: 1.6570x; 1.6570x over previous
#include <cuda_runtime.h>

#define NN    128
#define BATCH 2
#define LL    2048
#define CH    32          // chunk length S
#define NG    (LL/CH)     // 64 chunks per batch
#define NT    512         // threads for split-K kernels
#define PIT   129         // smem pitch (conflict-free)

// ---- device scratch (no allocation allowed) ----
__device__ float g_Ad[NN*NN];
__device__ float g_Bd[NN];
__device__ float g_pow[2][NN*NN];      // for Ad^S via squaring
__device__ float g_h[BATCH*NG*NN];     // local chunk contributions
__device__ float g_bound[BATCH*NG*NN]; // state entering each chunk

// ============================================================
// Kernel 1: SETUP (one launch replaces disc + 5x squaring).
// Cluster of 8 CTAs x 1024 threads.
//  - rank 0: D&C triangular inverse of P1 = I - 0.5A (lower tri),
//            Ad = 2*Minv - I, Bd = Minv*B  -> g_Ad, g_Bd, g_pow[0]
//  - all ranks: 5 squaring rounds (each block computes 16 rows),
//    separated by cluster barriers. Stores drain to L2 (+threadfence);
//    reload with __ldcg (L1-bypass) so no stale L1 reads.
// ============================================================
__global__ __launch_bounds__(1024, 1) __cluster_dims__(8, 1, 1)
void k_setup(const float* __restrict__ A, const float* __restrict__ B) {
    extern __shared__ float sm[];
    int tid = threadIdx.x;
    unsigned rank;
    asm("mov.u32 %0, %%cluster_ctarank;" : "=r"(rank));

    if (rank == 0) {
        float* sP = sm;                 // NN*PIT
        float* sM = sm + NN*PIT;        // NN*PIT
        float* sT = sm + 2*NN*PIT;      // 4096 temp

        for (int idx = tid; idx < NN*NN; idx += 1024) {
            int i = idx >> 7, j = idx & (NN-1);
            float iv = (i == j) ? 1.0f : 0.0f;
            sP[i*PIT + j] = iv - 0.5f * A[idx];
            sM[i*PIT + j] = 0.0f;
        }
        __syncthreads();

        // base: 16 diagonal 8x8 blocks, forward substitution
        if (tid < 128) {
            int blk = tid >> 3, col = tid & 7;
            int b0 = blk * 8;
            float x[8];
            #pragma unroll
            for (int i = 0; i < 8; i++) x[i] = 0.0f;
            for (int i = col; i < 8; i++) {
                float v = (i == col) ? 1.0f : 0.0f;
                for (int k = col; k < i; k++)
                    v -= sP[(b0+i)*PIT + b0 + k] * x[k];
                x[i] = v / sP[(b0+i)*PIT + b0 + i];
            }
            #pragma unroll
            for (int i = 0; i < 8; i++)
                sM[(b0+i)*PIT + b0 + col] = x[i];
        }
        __syncthreads();

        // 4 combine levels
        for (int s = 8; s <= 64; s <<= 1) {
            int npairs = NN / (2*s);
            int total  = npairs * s * s;
            for (int idx = tid; idx < total; idx += 1024) {
                int p = idx / (s*s);
                int rem = idx - p*s*s;
                int i = rem / s, j = rem - i*s;
                int r0 = 2*p*s;
                float acc = 0.0f;
                for (int k = 0; k < s; k++)
                    acc = fmaf(sM[(r0+s+i)*PIT + r0+s+k],
                               sP[(r0+s+k)*PIT + r0+j], acc);
                sT[idx] = acc;
            }
            __syncthreads();
            for (int idx = tid; idx < total; idx += 1024) {
                int p = idx / (s*s);
                int rem = idx - p*s*s;
                int i = rem / s, j = rem - i*s;
                int r0 = 2*p*s;
                float acc = 0.0f;
                const float* tp = sT + p*s*s + i*s;
                for (int k = 0; k < s; k++)
                    acc = fmaf(tp[k], sM[(r0+k)*PIT + r0+j], acc);
                sM[(r0+s+i)*PIT + r0+j] = -acc;
            }
            __syncthreads();
        }

        for (int idx = tid; idx < NN*NN; idx += 1024) {
            int i = idx >> 7, j = idx & (NN-1);
            float m = sM[i*PIT + j];
            float ad = 2.0f * m - ((i == j) ? 1.0f : 0.0f);
            g_Ad[idx] = ad;
            g_pow[0][idx] = ad;
        }
        if (tid < NN) {
            float acc = 0.0f;
            for (int j = 0; j <= tid; j++)
                acc = fmaf(sM[tid*PIT + j], B[j], acc);
            g_Bd[tid] = acc;
        }
    }
    __threadfence();
    __syncthreads();
    asm volatile("barrier.cluster.arrive.aligned;" ::: "memory");
    asm volatile("barrier.cluster.wait.aligned;"   ::: "memory");

    // ---- 5 squarings: src/dst alternate, end in g_pow[1] ----
    float*  sB  = sm;                   // reuse first 64KB
    float4* sB4 = (float4*)sB;
    for (int it = 0; it < 5; it++) {
        const float4* s4 = (const float4*)g_pow[it & 1];
        float* dst = g_pow[(it & 1) ^ 1];
        // stage full src (64KB) via L1-bypassing loads
        #pragma unroll
        for (int u = 0; u < 4; u++)
            sB4[tid + 1024*u] = __ldcg(s4 + tid + 1024*u);
        __syncthreads();
        // compute 16 rows: thread t<256 -> rows (rank*16 + t>>5) and +8
        if (tid < 256) {
            int row_a = rank*16 + (tid >> 5);
            int row_b = row_a + 8;
            int c4 = tid & 31;
            const float* ra = sB + row_a*NN;
            const float* rb = sB + row_b*NN;
            float4 acc0 = make_float4(0.f,0.f,0.f,0.f);
            float4 acc1 = make_float4(0.f,0.f,0.f,0.f);
            #pragma unroll 8
            for (int k = 0; k < NN; k++) {
                float4 bv = sB4[k*32 + c4];
                float a0 = ra[k], a1 = rb[k];
                acc0.x = fmaf(a0, bv.x, acc0.x);
                acc0.y = fmaf(a0, bv.y, acc0.y);
                acc0.z = fmaf(a0, bv.z, acc0.z);
                acc0.w = fmaf(a0, bv.w, acc0.w);
                acc1.x = fmaf(a1, bv.x, acc1.x);
                acc1.y = fmaf(a1, bv.y, acc1.y);
                acc1.z = fmaf(a1, bv.z, acc1.z);
                acc1.w = fmaf(a1, bv.w, acc1.w);
            }
            ((float4*)(dst + row_a*NN))[c4] = acc0;
            ((float4*)(dst + row_b*NN))[c4] = acc1;
        }
        __threadfence();
        __syncthreads();
        asm volatile("barrier.cluster.arrive.aligned;" ::: "memory");
        asm volatile("barrier.cluster.wait.aligned;"   ::: "memory");
    }
}

// ============================================================
// Kernel 2: phase A, 512 threads, 4-way split-K (round-8 design).
// Thread (r = tid&127, q = tid>>7) owns Ad[r, 32q:32q+32] in regs.
// ============================================================
__global__ __launch_bounds__(NT, 1) void k_phaseA(const float* __restrict__ f) {
    extern __shared__ float sm[];
    float* sAd = sm;               // NN*PIT
    float* sc  = sAd + NN*PIT;     // NN
    float* sf  = sc + NN;          // CH
    float* sp  = sf + CH;          // NT partials
    int tid = threadIdx.x;
    int r = tid & (NN-1), q = tid >> 7;
    int g = blockIdx.x, b = blockIdx.y;

    for (int idx = tid; idx < NN*NN; idx += NT) {
        int i = idx >> 7, j = idx & (NN-1);
        sAd[i*PIT + j] = g_Ad[idx];
    }
    if (tid < CH) sf[tid] = f[b*LL + g*CH + tid];
    if (tid < NN) sc[tid] = 0.0f;
    __syncthreads();

    float a[32];
    #pragma unroll
    for (int u = 0; u < 32; u++) a[u] = sAd[r*PIT + 32*q + u];
    float bd = (q == 0) ? g_Bd[r] : 0.0f;

    float cn = 0.0f;
    for (int t = 0; t < CH; t++) {
        float acc0 = (q == 0) ? bd * sf[t] : 0.f;
        float acc1 = 0.f, acc2 = 0.f, acc3 = 0.f;
        const float4* sc4 = (const float4*)sc;
        #pragma unroll
        for (int u4 = 0; u4 < 8; u4++) {
            float4 v = sc4[8*q + u4];
            acc0 = fmaf(a[4*u4+0], v.x, acc0);
            acc1 = fmaf(a[4*u4+1], v.y, acc1);
            acc2 = fmaf(a[4*u4+2], v.z, acc2);
            acc3 = fmaf(a[4*u4+3], v.w, acc3);
        }
        sp[q*NN + r] = (acc0 + acc1) + (acc2 + acc3);
        __syncthreads();
        if (q == 0) {
            cn = (sp[r] + sp[NN+r]) + (sp[2*NN+r] + sp[3*NN+r]);
            sc[r] = cn;
        }
        __syncthreads();
    }
    if (q == 0) g_h[(b*NG + g)*NN + r] = cn;
}

// ============================================================
// Kernel 3: boundary prefix, 512 threads, 4-way split-K.
// C_{g+1} = Ad^S * C_g + h_g.  One block per batch.
// ============================================================
__global__ __launch_bounds__(NT, 1) void k_phaseB() {
    extern __shared__ float sm[];
    float* sA = sm;             // NN*PIT
    float* sc = sA + NN*PIT;    // NN
    float* sp = sc + NN;        // NT
    int tid = threadIdx.x;
    int r = tid & (NN-1), q = tid >> 7;
    int b = blockIdx.x;
    const float* AdS = g_pow[1];   // Ad^32 after 5 squarings
    for (int idx = tid; idx < NN*NN; idx += NT) {
        int i = idx >> 7, j = idx & (NN-1);
        sA[i*PIT + j] = AdS[idx];
    }
    if (tid < NN) sc[tid] = 0.0f;
    __syncthreads();
    float a[32];
    #pragma unroll
    for (int u = 0; u < 32; u++) a[u] = sA[r*PIT + 32*q + u];

    float cn = 0.0f;
    for (int g = 0; g < NG; g++) {
        if (q == 0) g_bound[(b*NG + g)*NN + r] = cn;
        float acc0 = (q == 0) ? __ldg(g_h + (b*NG + g)*NN + r) : 0.f;
        float acc1 = 0.f, acc2 = 0.f, acc3 = 0.f;
        const float4* sc4 = (const float4*)sc;
        #pragma unroll
        for (int u4 = 0; u4 < 8; u4++) {
            float4 v = sc4[8*q + u4];
            acc0 = fmaf(a[4*u4+0], v.x, acc0);
            acc1 = fmaf(a[4*u4+1], v.y, acc1);
            acc2 = fmaf(a[4*u4+2], v.z, acc2);
            acc3 = fmaf(a[4*u4+3], v.w, acc3);
        }
        sp[q*NN + r] = (acc0 + acc1) + (acc2 + acc3);
        __syncthreads();
        if (q == 0) {
            cn = (sp[r] + sp[NN+r]) + (sp[2*NN+r] + sp[3*NN+r]);
            sc[r] = cn;
        }
        __syncthreads();
    }
}

// ============================================================
// Kernel 4: FUSED phase C + expand, TWO-PASS (round-8 design).
// Pass 1: 32-step recurrence into smem state buffer.
// Pass 2: barrier-free streaming store (1 LDS.128 + 8 STG.128 per t).
// ============================================================
__global__ __launch_bounds__(NT, 1) void k_fusedC(const float* __restrict__ f,
                                                  const float* __restrict__ Cv,
                                                  const float* __restrict__ Dv,
                                                  float* __restrict__ ys,
                                                  float* __restrict__ cfin) {
    extern __shared__ float sm[];
    float* sAd = sm;               // NN*PIT
    float* sSt = sAd + NN*PIT;     // CH*NN states
    float* sc  = sSt + CH*NN;      // NN current state
    float* sf  = sc + NN;          // CH
    float* sC  = sf + CH;          // NN
    float* sp  = sC + NN;          // NT
    int tid = threadIdx.x;
    int r = tid & (NN-1), q = tid >> 7;
    int g = blockIdx.x, b = blockIdx.y;

    for (int idx = tid; idx < NN*NN; idx += NT) {
        int i = idx >> 7, j = idx & (NN-1);
        sAd[i*PIT + j] = g_Ad[idx];
    }
    if (tid < CH) sf[tid] = f[b*LL + g*CH + tid];
    if (tid < NN) {
        sC[tid] = Cv[tid];
        sc[tid] = g_bound[(b*NG + g)*NN + tid];
    }
    __syncthreads();

    float a[32];
    #pragma unroll
    for (int u = 0; u < 32; u++) a[u] = sAd[r*PIT + 32*q + u];
    float bd  = (q == 0) ? g_Bd[r] : 0.0f;
    float dv0 = Dv[0];

    // ---- pass 1: recurrence into sSt ----
    for (int t = 0; t < CH; t++) {
        float acc0 = (q == 0) ? bd * sf[t] : 0.f;
        float acc1 = 0.f, acc2 = 0.f, acc3 = 0.f;
        const float4* sc4 = (const float4*)sc;
        #pragma unroll
        for (int u4 = 0; u4 < 8; u4++) {
            float4 v = sc4[8*q + u4];
            acc0 = fmaf(a[4*u4+0], v.x, acc0);
            acc1 = fmaf(a[4*u4+1], v.y, acc1);
            acc2 = fmaf(a[4*u4+2], v.z, acc2);
            acc3 = fmaf(a[4*u4+3], v.w, acc3);
        }
        sp[q*NN + r] = (acc0 + acc1) + (acc2 + acc3);
        __syncthreads();
        if (q == 0) {
            float cn = (sp[r] + sp[NN+r]) + (sp[2*NN+r] + sp[3*NN+r]);
            sc[r] = cn;
            sSt[t*NN + r] = cn;
        }
        __syncthreads();
    }

    // ---- pass 2: barrier-free streaming store ----
    float cn_[8];
    int nb = tid >> 5;
    #pragma unroll
    for (int it = 0; it < 8; it++) cn_[it] = sC[nb + 16*it];
    int lane = tid & 31;
    float4* outbase = (float4*)(ys + (size_t)(b*LL + g*CH) * NN * NN);
    const float4* st4 = (const float4*)sSt;

    for (int t = 0; t < CH; t++) {
        float4 cv = st4[t*(NN/4) + lane];
        float  df = dv0 * sf[t];
        float4* out = outbase + (size_t)t * (NN*NN/4);
        #pragma unroll
        for (int it = 0; it < 8; it++) {
            int idx = tid + NT*it;
            float4 v;
            v.x = fmaf(cn_[it], cv.x, df);
            v.y = fmaf(cn_[it], cv.y, df);
            v.z = fmaf(cn_[it], cv.z, df);
            v.w = fmaf(cn_[it], cv.w, df);
            __stcs(&out[idx], v);
        }
    }
    if (cfin != nullptr && g == NG-1 && tid < NN)
        cfin[b*NN + tid] = sSt[(CH-1)*NN + tid];
}

// ============================================================
extern "C" void kernel_launch(void* const* d_in, const int* in_sizes, int n_in,
                              void* d_out, int out_size) {
    const float* f = (const float*)d_in[0];
    const float* A = (const float*)d_in[1];
    const float* B = (const float*)d_in[2];
    const float* C = (const float*)d_in[3];
    const float* D = (const float*)d_in[4];
    float* out = (float*)d_out;

    const long long ysz = (long long)BATCH * LL * NN * NN;   // 67108864
    const int cf = BATCH * NN;                               // 256
    float* cfin = nullptr;
    float* ys   = out;
    if ((long long)out_size == ysz + cf) { cfin = out; ys = out + cf; }

    const int smem_setup = (2*NN*PIT + 4096)*4;              // 148480
    const int smem_pA    = (NN*PIT + NN + CH + NT)*4;        // 68736
    const int smem_pB    = (NN*PIT + NN + NT)*4;             // 68608
    const int smem_fC    = (NN*PIT + CH*NN + NN + CH + NN + NT)*4; // 85632
    cudaFuncSetAttribute(k_setup,  cudaFuncAttributeMaxDynamicSharedMemorySize, smem_setup);
    cudaFuncSetAttribute(k_phaseA, cudaFuncAttributeMaxDynamicSharedMemorySize, smem_pA);
    cudaFuncSetAttribute(k_phaseB, cudaFuncAttributeMaxDynamicSharedMemorySize, smem_pB);
    cudaFuncSetAttribute(k_fusedC, cudaFuncAttributeMaxDynamicSharedMemorySize, smem_fC);

    // 1) setup: discretize + Ad^32 (cluster kernel, one launch)
    k_setup<<<8, 1024, smem_setup>>>(A, B);
    // 2) phase A — local chunk contributions
    dim3 gA(NG, BATCH);
    k_phaseA<<<gA, NT, smem_pA>>>(f);
    // 3) boundary prefix
    k_phaseB<<<BATCH, NT, smem_pB>>>();
    // 4) fused phase C + expand: 268MB streaming store
    k_fusedC<<<gA, NT, smem_fC>>>(f, C, D, ys, cfin);
}